// round 14
// baseline (speedup 1.0000x reference)
#include <cuda_runtime.h>
#include <cuda_fp16.h>
#include <cstdint>

#define EMBED  512
#define CONVC  512
#define HID    1024
#define LABELS 128
#define M_TOTAL (32 * 1024)

// Scratch (allocation-free rule -> __device__ globals). fp16 payloads.
__device__ __half g_x[(size_t)M_TOTAL * EMBED];   // gathered fp16 embeddings, 32 MB
__device__ __half g_h[(size_t)M_TOTAL * CONVC];   // 32 MB
__device__ __half g_z[(size_t)M_TOTAL * HID];     // 64 MB
__device__ __half g_w0[(size_t)CONVC * EMBED];    // conv_w fp16 [N,K]
__device__ __half g_w1t[(size_t)HID * CONVC];     // w1^T fp16 [1024,512]
__device__ __half g_w2t[(size_t)LABELS * HID];    // w2^T fp16 [128,1024]

__device__ __forceinline__ uint32_t smem_u32(const void* p) {
    uint32_t a;
    asm("{ .reg .u64 t; cvta.to.shared.u64 t, %1; cvt.u32.u64 %0, t; }" : "=r"(a) : "l"(p));
    return a;
}

#define CP_ASYNC16(dst, src) \
    asm volatile("cp.async.cg.shared.global [%0], [%1], 16;" :: "r"(dst), "l"(src))
#define CP_COMMIT() asm volatile("cp.async.commit_group;" ::: "memory")
#define CP_WAIT1()  asm volatile("cp.async.wait_group 1;" ::: "memory")

#define LDSM_X4(r0, r1, r2, r3, addr) \
    asm volatile("ldmatrix.sync.aligned.m8n8.x4.shared.b16 {%0,%1,%2,%3}, [%4];" \
        : "=r"(r0), "=r"(r1), "=r"(r2), "=r"(r3) : "r"(addr))

__device__ __forceinline__ void mma_f16(float* c, const uint32_t* a, const uint32_t* b) {
    asm volatile(
        "mma.sync.aligned.m16n8k16.row.col.f32.f16.f16.f32 "
        "{%0,%1,%2,%3}, {%4,%5,%6,%7}, {%8,%9}, {%0,%1,%2,%3};\n"
        : "+f"(c[0]), "+f"(c[1]), "+f"(c[2]), "+f"(c[3])
        : "r"(a[0]), "r"(a[1]), "r"(a[2]), "r"(a[3]), "r"(b[0]), "r"(b[1]));
}

// ---------- continuous-ring persistent fp16 GEMM, 3 CTAs/SM ----------
// C[M, N_TOTAL] = act(A[M,K] @ Wt[N,K]^T + bias). A, Wt fp16; accumulate fp32.
// BM=128, BN=64, BK=64 halves. 8 warps (4m x 2n), warp tile 32x32 (acc = 32 regs).
// 2-stage cp.async ring (two barriers per chunk), continuous across tiles.
template <int N_TOTAL, int K, bool RELU, bool HALF_OUT>
__global__ __launch_bounds__(256, 3)
void gemm_pipe_h(const __half* __restrict__ A, const __half* __restrict__ Wt,
                 const float* __restrict__ bias, void* __restrict__ Cv) {
    constexpr int BM = 128, BN = 64, BK = 64;      // BK in halves = 128 B
    constexpr int KCH = K / BK;
    constexpr int MI  = 2;                          // m16-frags per warp (32 rows)
    constexpr int NI  = 4;                          // n8-frags per warp (32 cols)
    constexpr int P32 = 36;                         // u32 per smem row (72 halves, pad 8)
    constexpr int ROWB = P32 * 4;                   // 144 bytes
    constexpr int A_BYTES = BM * ROWB;              // 18432
    constexpr int B_BYTES = BN * ROWB;              // 9216
    constexpr int STAGE = A_BYTES + B_BYTES;        // 27648 (x2 = 55296)
    constexpr int NTX = N_TOTAL / BN;
    constexpr int NTILES = (M_TOTAL / BM) * NTX;

    extern __shared__ char smem[];
    const uint32_t sb = smem_u32(smem);

    const int tid  = threadIdx.x;
    const int warp = tid >> 5, lane = tid & 31;
    const int grp  = lane >> 2, tig = lane & 3;
    const int wm   = warp >> 1, wn = warp & 1;

    // ldmatrix per-lane byte offsets (tile-invariant)
    const int j  = lane >> 3;                       // 0..3
    const int r8 = lane & 7;
    uint32_t offA[MI], offB[2];
#pragma unroll
    for (int mi = 0; mi < MI; mi++)                 // A x4: (m0-7,k0-7)(m8-15,k0-7)(m0-7,k8-15)(m8-15,k8-15)
        offA[mi] = (uint32_t)((wm * 32 + mi * 16 + (j & 1) * 8 + r8) * ROWB + (j >> 1) * 16);
#pragma unroll
    for (int p = 0; p < 2; p++)                     // B pair: n-frags 2p, 2p+1
        offB[p] = (uint32_t)((wn * 32 + p * 16 + ((lane >> 4) & 1) * 8 + r8) * ROWB + ((lane >> 3) & 1) * 16);

    const int ldr = tid >> 3, ldc = tid & 7;        // stage-fill row/col

    // issue chunk c (global per-CTA chunk stream index) into ring stage c%2
    auto issue = [&](int c) {
        const int t  = blockIdx.x + (c / KCH) * gridDim.x;
        if (t >= NTILES) return;
        const int kt = c % KCH;
        const int bm = (t / NTX) * BM;
        const int bn = (t % NTX) * BN;
        const int k0 = kt * BK;
        const uint32_t ab = sb + (c & 1) * STAGE;
        const uint32_t bb = ab + A_BYTES;
#pragma unroll
        for (int i = 0; i < 4; i++) {               // A: 128 rows x 8 chunks
            int r = ldr + i * 32;
            CP_ASYNC16(ab + (uint32_t)(r * ROWB + ldc * 16),
                       A + (size_t)(bm + r) * K + k0 + ldc * 8);
        }
#pragma unroll
        for (int i = 0; i < 2; i++) {               // B: 64 rows x 8 chunks
            int r = ldr + i * 32;
            CP_ASYNC16(bb + (uint32_t)(r * ROWB + ldc * 16),
                       Wt + (size_t)(bn + r) * K + k0 + ldc * 8);
        }
    };

    const int my_tiles = (NTILES - blockIdx.x + (int)gridDim.x - 1) / (int)gridDim.x;
    const int nch = my_tiles * KCH;
    if (nch == 0) return;

    float acc[MI][NI][4];
#pragma unroll
    for (int mi = 0; mi < MI; mi++)
#pragma unroll
        for (int ni = 0; ni < NI; ni++)
#pragma unroll
            for (int q = 0; q < 4; q++) acc[mi][ni][q] = 0.0f;

    issue(0); CP_COMMIT();
    issue(1); CP_COMMIT();

    for (int g = 0; g < nch; g++) {
        CP_WAIT1();                                 // chunk g landed (per-thread)
        __syncthreads();                            // visible CTA-wide

        const uint32_t sA = sb + (g & 1) * STAGE;
        const uint32_t sB = sA + A_BYTES;
#pragma unroll
        for (int ks = 0; ks < 4; ks++) {            // 4 x k16 steps, +32B each
            const int kb = ks * 32;
            uint32_t a[MI][4], b[NI][2];
#pragma unroll
            for (int mi = 0; mi < MI; mi++)
                LDSM_X4(a[mi][0], a[mi][1], a[mi][2], a[mi][3], sA + offA[mi] + kb);
#pragma unroll
            for (int p = 0; p < 2; p++)
                LDSM_X4(b[2 * p][0], b[2 * p][1], b[2 * p + 1][0], b[2 * p + 1][1],
                        sB + offB[p] + kb);
#pragma unroll
            for (int mi = 0; mi < MI; mi++)
#pragma unroll
                for (int ni = 0; ni < NI; ni++)
                    mma_f16(acc[mi][ni], a[mi], b[ni]);
        }

        // tile finished? -> epilogue (no smem)
        if ((g % KCH) == KCH - 1) {
            const int t  = blockIdx.x + (g / KCH) * gridDim.x;
            const int bm = (t / NTX) * BM;
            const int bn = (t % NTX) * BN;
#pragma unroll
            for (int ni = 0; ni < NI; ni++) {
                const int n = bn + wn * 32 + ni * 8 + tig * 2;
                const float bv0 = __ldg(&bias[n]);
                const float bv1 = __ldg(&bias[n + 1]);
#pragma unroll
                for (int mi = 0; mi < MI; mi++) {
                    const int m0 = bm + wm * 32 + mi * 16 + grp;
                    float v0 = acc[mi][ni][0] + bv0;
                    float v1 = acc[mi][ni][1] + bv1;
                    float v2 = acc[mi][ni][2] + bv0;
                    float v3 = acc[mi][ni][3] + bv1;
                    if (RELU) {
                        v0 = fmaxf(v0, 0.0f); v1 = fmaxf(v1, 0.0f);
                        v2 = fmaxf(v2, 0.0f); v3 = fmaxf(v3, 0.0f);
                    }
                    if (HALF_OUT) {
                        __half* C = (__half*)Cv;
                        *(__half2*)(C + (size_t)m0 * N_TOTAL + n)       = __floats2half2_rn(v0, v1);
                        *(__half2*)(C + (size_t)(m0 + 8) * N_TOTAL + n) = __floats2half2_rn(v2, v3);
                    } else {
                        float* C = (float*)Cv;
                        *(float2*)(C + (size_t)m0 * N_TOTAL + n)       = make_float2(v0, v1);
                        *(float2*)(C + (size_t)(m0 + 8) * N_TOTAL + n) = make_float2(v2, v3);
                    }
                    acc[mi][ni][0] = 0.0f; acc[mi][ni][1] = 0.0f;
                    acc[mi][ni][2] = 0.0f; acc[mi][ni][3] = 0.0f;
                }
            }
        }

        __syncthreads();                            // stage g%2 fully consumed
        issue(g + 2);                               // overwrite stage g%2 with chunk g+2
        CP_COMMIT();
    }
}

// ---------------- merged prep kernel ----------------
#define GATHER_BLOCKS (M_TOTAL * EMBED / 8 / 256)   // 8192
__global__ __launch_bounds__(256)
void prep_kernel(const int* __restrict__ tok, const float* __restrict__ emb,
                 __half* __restrict__ x,
                 const float* __restrict__ conv_w, __half* __restrict__ w0,
                 const float* __restrict__ w1, __half* __restrict__ w1t,
                 const float* __restrict__ w2, __half* __restrict__ w2t) {
    const int b = blockIdx.x;
    const int tid = threadIdx.x;
    if (b < GATHER_BLOCKS) {
        const int base = (b * 256 + tid) * 2;
#pragma unroll
        for (int u = 0; u < 2; u++) {
            const int i4 = base + u;
            const int row = i4 >> 7;                // EMBED/4 = 128
            const int c   = (i4 & 127) << 2;
            const float4 v = *(const float4*)(emb + (size_t)tok[row] * EMBED + c);
            __half2 h0 = __floats2half2_rn(v.x, v.y);
            __half2 h1 = __floats2half2_rn(v.z, v.w);
            *(uint2*)(x + (size_t)row * EMBED + c) = make_uint2(*(uint32_t*)&h0, *(uint32_t*)&h1);
        }
        return;
    }
    const int wb = b - GATHER_BLOCKS;
    if (wb < 256) {                                 // cvt conv_w
        const int i4 = wb * 256 + tid;
        const float4 v = *(const float4*)(conv_w + (size_t)i4 * 4);
        __half2 h0 = __floats2half2_rn(v.x, v.y);
        __half2 h1 = __floats2half2_rn(v.z, v.w);
        *(uint2*)(w0 + (size_t)i4 * 4) = make_uint2(*(uint32_t*)&h0, *(uint32_t*)&h1);
        return;
    }
    const float* in; __half* outp; int R, Ccols, tb;
    if (wb < 768) { in = w1; outp = w1t; R = CONVC; Ccols = HID;    tb = wb - 256; }
    else          { in = w2; outp = w2t; R = HID;   Ccols = LABELS; tb = wb - 768; }
    const int tpr = Ccols / 32;
    const int by = (tb / tpr) * 32, bx = (tb % tpr) * 32;
    const int tx = tid & 31, ty = tid >> 5;
    __shared__ float t[32][33];
    int x2 = bx + tx;
#pragma unroll
    for (int jj = 0; jj < 32; jj += 8) {
        int y = by + ty + jj;
        t[ty + jj][tx] = in[(size_t)y * Ccols + x2];
    }
    __syncthreads();
    x2 = by + tx;
#pragma unroll
    for (int jj = 0; jj < 32; jj += 8) {
        int y = bx + ty + jj;
        outp[(size_t)y * R + x2] = __float2half_rn(t[tx][ty + jj]);
    }
}

extern "C" void kernel_launch(void* const* d_in, const int* in_sizes, int n_in,
                              void* d_out, int out_size) {
    const int*   tok    = (const int*)d_in[0];
    const float* emb    = (const float*)d_in[1];
    const float* conv_w = (const float*)d_in[2];   // [CONVC, EMBED] = [N,K]
    const float* conv_b = (const float*)d_in[3];
    const float* w1     = (const float*)d_in[4];   // [CONVC, HID]
    const float* b1     = (const float*)d_in[5];
    const float* w2     = (const float*)d_in[6];   // [HID, LABELS]
    const float* b2     = (const float*)d_in[7];
    float* out = (float*)d_out;

    __half *x_buf, *h_buf, *z_buf, *w0, *w1t, *w2t;
    cudaGetSymbolAddress((void**)&x_buf, g_x);
    cudaGetSymbolAddress((void**)&h_buf, g_h);
    cudaGetSymbolAddress((void**)&z_buf, g_z);
    cudaGetSymbolAddress((void**)&w0,  g_w0);
    cudaGetSymbolAddress((void**)&w1t, g_w1t);
    cudaGetSymbolAddress((void**)&w2t, g_w2t);

    constexpr int SMEM = 2 * (128 * 144 + 64 * 144);    // 55296 -> 3 CTAs/SM
    cudaFuncSetAttribute(gemm_pipe_h<CONVC, EMBED, true,  true>,
                         cudaFuncAttributeMaxDynamicSharedMemorySize, SMEM);
    cudaFuncSetAttribute(gemm_pipe_h<HID, CONVC, true,  true>,
                         cudaFuncAttributeMaxDynamicSharedMemorySize, SMEM);
    cudaFuncSetAttribute(gemm_pipe_h<LABELS, HID, false, false>,
                         cudaFuncAttributeMaxDynamicSharedMemorySize, SMEM);

    constexpr int PERSIST = 444;                    // 148 SMs x 3 CTAs

    // Prep (one kernel: gather + all weight conversions)
    prep_kernel<<<GATHER_BLOCKS + 896, 256>>>(tok, emb, x_buf, conv_w, w0, w1, w1t, w2, w2t);

    // GEMM1: h = fp16(relu(x @ conv_w^T + conv_b))    [32768, 512], 2048 tiles
    gemm_pipe_h<CONVC, EMBED, true, true>
        <<<PERSIST, 256, SMEM>>>(x_buf, w0, conv_b, h_buf);
    // GEMM2: z = fp16(relu(h @ w1 + b1))              [32768, 1024], 4096 tiles
    gemm_pipe_h<HID, CONVC, true, true>
        <<<PERSIST, 256, SMEM>>>(h_buf, w1t, b1, z_buf);
    // GEMM3: out = z @ w2 + b2                        [32768, 128], 512 tiles
    gemm_pipe_h<LABELS, HID, false, false>
        <<<PERSIST, 256, SMEM>>>(z_buf, w2t, b2, out);
}

// round 15
// speedup vs baseline: 1.5704x; 1.5704x over previous
#include <cuda_runtime.h>
#include <cuda_fp16.h>
#include <cstdint>

#define EMBED  512
#define CONVC  512
#define HID    1024
#define LABELS 128
#define M_TOTAL (32 * 1024)

// Scratch (allocation-free rule -> __device__ globals). fp16 payloads.
__device__ __half g_x[(size_t)M_TOTAL * EMBED];   // gathered fp16 embeddings, 32 MB
__device__ __half g_h[(size_t)M_TOTAL * CONVC];   // 32 MB
__device__ __half g_z[(size_t)M_TOTAL * HID];     // 64 MB
__device__ __half g_w0[(size_t)CONVC * EMBED];    // conv_w fp16 [N,K]
__device__ __half g_w1t[(size_t)HID * CONVC];     // w1^T fp16 [1024,512]
__device__ __half g_w2t[(size_t)LABELS * HID];    // w2^T fp16 [128,1024]

__device__ __forceinline__ uint32_t smem_u32(const void* p) {
    uint32_t a;
    asm("{ .reg .u64 t; cvta.to.shared.u64 t, %1; cvt.u32.u64 %0, t; }" : "=r"(a) : "l"(p));
    return a;
}

#define CP_ASYNC16(dst, src) \
    asm volatile("cp.async.cg.shared.global [%0], [%1], 16;" :: "r"(dst), "l"(src))
#define CP_COMMIT() asm volatile("cp.async.commit_group;" ::: "memory")
#define CP_WAIT1()  asm volatile("cp.async.wait_group 1;" ::: "memory")

#define LDSM_X4(r0, r1, r2, r3, addr) \
    asm volatile("ldmatrix.sync.aligned.m8n8.x4.shared.b16 {%0,%1,%2,%3}, [%4];" \
        : "=r"(r0), "=r"(r1), "=r"(r2), "=r"(r3) : "r"(addr))

#define RED_ADD_F32(ptr, v) \
    asm volatile("red.global.add.f32 [%0], %1;" :: "l"(ptr), "f"(v) : "memory")

__device__ __forceinline__ void mma_f16(float* c, const uint32_t* a, const uint32_t* b) {
    asm volatile(
        "mma.sync.aligned.m16n8k16.row.col.f32.f16.f16.f32 "
        "{%0,%1,%2,%3}, {%4,%5,%6,%7}, {%8,%9}, {%0,%1,%2,%3};\n"
        : "+f"(c[0]), "+f"(c[1]), "+f"(c[2]), "+f"(c[3])
        : "r"(a[0]), "r"(a[1]), "r"(a[2]), "r"(a[3]), "r"(b[0]), "r"(b[1]));
}

// ---------- continuous-ring persistent fp16 GEMM, 2 CTAs/SM ----------
// C[M, N_TOTAL] = act(A[M,K] @ Wt[N,K]^T + bias). A, Wt fp16; accumulate fp32.
// BM=128, BN=128, BK=64 halves. 8 warps (4m x 2n), warp tile 32x64.
// All (job, chunk) pairs per CTA form ONE chunk stream over a 3-stage cp.async
// ring: no per-tile drain/refill; epilogue overlaps next tile's loads.
// KSLICES>1: split-K; C must be pre-initialized with bias; partials red.add'd.
template <int N_TOTAL, int K, int KSLICES, bool RELU, bool HALF_OUT>
__global__ __launch_bounds__(256, 2)
void gemm_pipe_h(const __half* __restrict__ A, const __half* __restrict__ Wt,
                 const float* __restrict__ bias, void* __restrict__ Cv) {
    constexpr int BM = 128, BN = 128, BK = 64;     // BK in halves = 128 B
    constexpr int KSL = K / KSLICES;                // K per slice (halves)
    constexpr int KCH = KSL / BK;                   // chunks per job
    constexpr int MI  = 2;                          // m16-frags per warp (32 rows)
    constexpr int P32 = 36;                         // u32 per smem row (72 halves, pad 8)
    constexpr int ROWB = P32 * 4;                   // 144 bytes
    constexpr int A_BYTES = BM * ROWB;              // 18432
    constexpr int B_BYTES = BN * ROWB;              // 18432
    constexpr int STAGE = A_BYTES + B_BYTES;        // 36864 (x3 = 110592)
    constexpr int NTX = N_TOTAL / BN;
    constexpr int JOBS_PER_K = (M_TOTAL / BM) * NTX;
    constexpr int NTILES = JOBS_PER_K * KSLICES;

    extern __shared__ char smem[];
    const uint32_t sb = smem_u32(smem);

    const int tid  = threadIdx.x;
    const int warp = tid >> 5, lane = tid & 31;
    const int grp  = lane >> 2, tig = lane & 3;
    const int wm   = warp >> 1, wn = warp & 1;

    // ldmatrix per-lane byte offsets (tile-invariant)
    const int j  = lane >> 3;                       // 0..3
    const int r8 = lane & 7;
    uint32_t offA[MI], offB[4];
#pragma unroll
    for (int mi = 0; mi < MI; mi++)                 // A x4: (m0-7,k0-7)(m8-15,k0-7)(m0-7,k8-15)(m8-15,k8-15)
        offA[mi] = (uint32_t)((wm * 32 + mi * 16 + (j & 1) * 8 + r8) * ROWB + (j >> 1) * 16);
#pragma unroll
    for (int p = 0; p < 4; p++)                     // B pair: n-frags 2p, 2p+1
        offB[p] = (uint32_t)((wn * 64 + p * 16 + ((lane >> 4) & 1) * 8 + r8) * ROWB + ((lane >> 3) & 1) * 16);

    const int ldr = tid >> 3, ldc = tid & 7;        // stage-fill row/col

    // issue chunk c (global per-CTA chunk stream index) into ring stage c%3
    auto issue = [&](int c) {
        const int t  = blockIdx.x + (c / KCH) * gridDim.x;
        if (t >= NTILES) return;
        const int kt  = c % KCH;
        const int job = t % JOBS_PER_K;
        const int ksl = t / JOBS_PER_K;
        const int bm = (job / NTX) * BM;
        const int bn = (job % NTX) * BN;
        const int k0 = ksl * KSL + kt * BK;
        const uint32_t ab = sb + (c % 3) * STAGE;
        const uint32_t bb = ab + A_BYTES;
#pragma unroll
        for (int i = 0; i < 4; i++) {
            int r = ldr + i * 32;
            CP_ASYNC16(ab + (uint32_t)(r * ROWB + ldc * 16),
                       A + (size_t)(bm + r) * K + k0 + ldc * 8);
        }
#pragma unroll
        for (int i = 0; i < 4; i++) {
            int r = ldr + i * 32;
            CP_ASYNC16(bb + (uint32_t)(r * ROWB + ldc * 16),
                       Wt + (size_t)(bn + r) * K + k0 + ldc * 8);
        }
    };

    const int my_tiles = (NTILES - blockIdx.x + (int)gridDim.x - 1) / (int)gridDim.x;
    const int nch = my_tiles * KCH;
    if (nch == 0) return;

    float acc[MI][8][4];
#pragma unroll
    for (int mi = 0; mi < MI; mi++)
#pragma unroll
        for (int ni = 0; ni < 8; ni++)
#pragma unroll
            for (int q = 0; q < 4; q++) acc[mi][ni][q] = 0.0f;

    issue(0); CP_COMMIT();
    issue(1); CP_COMMIT();

    for (int g = 0; g < nch; g++) {
        const int s = g % 3;
        CP_WAIT1();                                 // chunk g landed
        __syncthreads();                            // chunk g-1 fully consumed by all warps
        issue(g + 2);                               // may belong to the next job
        CP_COMMIT();

        const uint32_t sA = sb + s * STAGE;
        const uint32_t sB = sA + A_BYTES;
#pragma unroll
        for (int ks = 0; ks < 4; ks++) {            // 4 x k16 steps, +32B each
            const int kb = ks * 32;
            uint32_t a[MI][4], b[8][2];
#pragma unroll
            for (int mi = 0; mi < MI; mi++)
                LDSM_X4(a[mi][0], a[mi][1], a[mi][2], a[mi][3], sA + offA[mi] + kb);
#pragma unroll
            for (int p = 0; p < 4; p++)
                LDSM_X4(b[2 * p][0], b[2 * p][1], b[2 * p + 1][0], b[2 * p + 1][1],
                        sB + offB[p] + kb);
#pragma unroll
            for (int mi = 0; mi < MI; mi++)
#pragma unroll
                for (int ni = 0; ni < 8; ni++)
                    mma_f16(acc[mi][ni], a[mi], b[ni]);
        }

        // job finished? -> epilogue (no smem; overlaps next job's cp.async)
        if ((g % KCH) == KCH - 1) {
            const int t   = blockIdx.x + (g / KCH) * gridDim.x;
            const int job = t % JOBS_PER_K;
            const int bm = (job / NTX) * BM;
            const int bn = (job % NTX) * BN;
#pragma unroll
            for (int ni = 0; ni < 8; ni++) {
                const int n = bn + wn * 64 + ni * 8 + tig * 2;
                float bv0 = 0.0f, bv1 = 0.0f;
                if (KSLICES == 1) { bv0 = __ldg(&bias[n]); bv1 = __ldg(&bias[n + 1]); }
#pragma unroll
                for (int mi = 0; mi < MI; mi++) {
                    const int m0 = bm + wm * 32 + mi * 16 + grp;
                    float v0 = acc[mi][ni][0] + bv0;
                    float v1 = acc[mi][ni][1] + bv1;
                    float v2 = acc[mi][ni][2] + bv0;
                    float v3 = acc[mi][ni][3] + bv1;
                    if (RELU) {
                        v0 = fmaxf(v0, 0.0f); v1 = fmaxf(v1, 0.0f);
                        v2 = fmaxf(v2, 0.0f); v3 = fmaxf(v3, 0.0f);
                    }
                    if (KSLICES > 1) {
                        float* C = (float*)Cv;
                        RED_ADD_F32(C + (size_t)m0 * N_TOTAL + n,           v0);
                        RED_ADD_F32(C + (size_t)m0 * N_TOTAL + n + 1,       v1);
                        RED_ADD_F32(C + (size_t)(m0 + 8) * N_TOTAL + n,     v2);
                        RED_ADD_F32(C + (size_t)(m0 + 8) * N_TOTAL + n + 1, v3);
                    } else if (HALF_OUT) {
                        __half* C = (__half*)Cv;
                        *(__half2*)(C + (size_t)m0 * N_TOTAL + n)       = __floats2half2_rn(v0, v1);
                        *(__half2*)(C + (size_t)(m0 + 8) * N_TOTAL + n) = __floats2half2_rn(v2, v3);
                    } else {
                        float* C = (float*)Cv;
                        *(float2*)(C + (size_t)m0 * N_TOTAL + n)       = make_float2(v0, v1);
                        *(float2*)(C + (size_t)(m0 + 8) * N_TOTAL + n) = make_float2(v2, v3);
                    }
                    acc[mi][ni][0] = 0.0f; acc[mi][ni][1] = 0.0f;
                    acc[mi][ni][2] = 0.0f; acc[mi][ni][3] = 0.0f;
                }
            }
        }
    }
}

// ---------------- merged prep kernel ----------------
#define GATHER_BLOCKS (M_TOTAL * EMBED / 8 / 256)   // 8192
__global__ __launch_bounds__(256)
void prep_kernel(const int* __restrict__ tok, const float* __restrict__ emb,
                 __half* __restrict__ x,
                 const float* __restrict__ conv_w, __half* __restrict__ w0,
                 const float* __restrict__ w1, __half* __restrict__ w1t,
                 const float* __restrict__ w2, __half* __restrict__ w2t) {
    const int b = blockIdx.x;
    const int tid = threadIdx.x;
    if (b < GATHER_BLOCKS) {
        const int base = (b * 256 + tid) * 2;
#pragma unroll
        for (int u = 0; u < 2; u++) {
            const int i4 = base + u;
            const int row = i4 >> 7;                // EMBED/4 = 128
            const int c   = (i4 & 127) << 2;
            const float4 v = *(const float4*)(emb + (size_t)tok[row] * EMBED + c);
            __half2 h0 = __floats2half2_rn(v.x, v.y);
            __half2 h1 = __floats2half2_rn(v.z, v.w);
            *(uint2*)(x + (size_t)row * EMBED + c) = make_uint2(*(uint32_t*)&h0, *(uint32_t*)&h1);
        }
        return;
    }
    const int wb = b - GATHER_BLOCKS;
    if (wb < 256) {                                 // cvt conv_w
        const int i4 = wb * 256 + tid;
        const float4 v = *(const float4*)(conv_w + (size_t)i4 * 4);
        __half2 h0 = __floats2half2_rn(v.x, v.y);
        __half2 h1 = __floats2half2_rn(v.z, v.w);
        *(uint2*)(w0 + (size_t)i4 * 4) = make_uint2(*(uint32_t*)&h0, *(uint32_t*)&h1);
        return;
    }
    const float* in; __half* outp; int R, Ccols, tb;
    if (wb < 768) { in = w1; outp = w1t; R = CONVC; Ccols = HID;    tb = wb - 256; }
    else          { in = w2; outp = w2t; R = HID;   Ccols = LABELS; tb = wb - 768; }
    const int tpr = Ccols / 32;
    const int by = (tb / tpr) * 32, bx = (tb % tpr) * 32;
    const int tx = tid & 31, ty = tid >> 5;
    __shared__ float t[32][33];
    int x2 = bx + tx;
#pragma unroll
    for (int jj = 0; jj < 32; jj += 8) {
        int y = by + ty + jj;
        t[ty + jj][tx] = in[(size_t)y * Ccols + x2];
    }
    __syncthreads();
    x2 = by + tx;
#pragma unroll
    for (int jj = 0; jj < 32; jj += 8) {
        int y = bx + ty + jj;
        outp[(size_t)y * R + x2] = __float2half_rn(t[tx][ty + jj]);
    }
}

// Initialize out[m][n] = b2[n] (split-K partials red.add on top)
__global__ __launch_bounds__(256)
void init_out_kernel(const float* __restrict__ b2, float* __restrict__ out) {
    const int i4 = blockIdx.x * 256 + threadIdx.x;  // 1048576 float4 total
    const int n4 = i4 & (LABELS / 4 - 1);           // 32 float4 per row
    ((float4*)out)[i4] = ((const float4*)b2)[n4];
}

extern "C" void kernel_launch(void* const* d_in, const int* in_sizes, int n_in,
                              void* d_out, int out_size) {
    const int*   tok    = (const int*)d_in[0];
    const float* emb    = (const float*)d_in[1];
    const float* conv_w = (const float*)d_in[2];   // [CONVC, EMBED] = [N,K]
    const float* conv_b = (const float*)d_in[3];
    const float* w1     = (const float*)d_in[4];   // [CONVC, HID]
    const float* b1     = (const float*)d_in[5];
    const float* w2     = (const float*)d_in[6];   // [HID, LABELS]
    const float* b2     = (const float*)d_in[7];
    float* out = (float*)d_out;

    __half *x_buf, *h_buf, *z_buf, *w0, *w1t, *w2t;
    cudaGetSymbolAddress((void**)&x_buf, g_x);
    cudaGetSymbolAddress((void**)&h_buf, g_h);
    cudaGetSymbolAddress((void**)&z_buf, g_z);
    cudaGetSymbolAddress((void**)&w0,  g_w0);
    cudaGetSymbolAddress((void**)&w1t, g_w1t);
    cudaGetSymbolAddress((void**)&w2t, g_w2t);

    constexpr int SMEM = 3 * (128 * 144 + 128 * 144);   // 110592 -> 2 CTAs/SM
    cudaFuncSetAttribute(gemm_pipe_h<CONVC, EMBED, 1, true,  true>,
                         cudaFuncAttributeMaxDynamicSharedMemorySize, SMEM);
    cudaFuncSetAttribute(gemm_pipe_h<HID, CONVC, 1, true,  true>,
                         cudaFuncAttributeMaxDynamicSharedMemorySize, SMEM);
    cudaFuncSetAttribute(gemm_pipe_h<LABELS, HID, 4, false, false>,
                         cudaFuncAttributeMaxDynamicSharedMemorySize, SMEM);

    constexpr int PERSIST = 296;                    // 148 SMs x 2 CTAs

    // Prep (gather + all weight conversions) and out = bias init for split-K
    prep_kernel<<<GATHER_BLOCKS + 896, 256>>>(tok, emb, x_buf, conv_w, w0, w1, w1t, w2, w2t);
    init_out_kernel<<<(M_TOTAL * LABELS / 4) / 256, 256>>>(b2, out);

    // GEMM1: h = fp16(relu(x @ conv_w^T + conv_b))    [32768, 512], 1024 jobs
    gemm_pipe_h<CONVC, EMBED, 1, true, true>
        <<<PERSIST, 256, SMEM>>>(x_buf, w0, conv_b, h_buf);
    // GEMM2: z = fp16(relu(h @ w1 + b1))              [32768, 1024], 2048 jobs
    gemm_pipe_h<HID, CONVC, 1, true, true>
        <<<PERSIST, 256, SMEM>>>(h_buf, w1t, b1, z_buf);
    // GEMM3: out += z @ w2 (split-K=4)                [32768, 128], 1024 jobs
    gemm_pipe_h<LABELS, HID, 4, false, false>
        <<<PERSIST, 256, SMEM>>>(z_buf, w2t, b2, out);
}

// round 16
// speedup vs baseline: 1.7158x; 1.0926x over previous
#include <cuda_runtime.h>
#include <cuda_fp16.h>
#include <cstdint>

#define EMBED  512
#define CONVC  512
#define HID    1024
#define LABELS 128
#define M_TOTAL (32 * 1024)

// Scratch (allocation-free rule -> __device__ globals). fp16 payloads.
__device__ __half g_x[(size_t)M_TOTAL * EMBED];   // gathered fp16 embeddings, 32 MB
__device__ __half g_h[(size_t)M_TOTAL * CONVC];   // 32 MB
__device__ __half g_z[(size_t)M_TOTAL * HID];     // 64 MB
__device__ __half g_w0[(size_t)CONVC * EMBED];    // conv_w fp16 [N,K]
__device__ __half g_w1t[(size_t)HID * CONVC];     // w1^T fp16 [1024,512]
__device__ __half g_w2t[(size_t)LABELS * HID];    // w2^T fp16 [128,1024]

__device__ __forceinline__ uint32_t smem_u32(const void* p) {
    uint32_t a;
    asm("{ .reg .u64 t; cvta.to.shared.u64 t, %1; cvt.u32.u64 %0, t; }" : "=r"(a) : "l"(p));
    return a;
}

#define CP_ASYNC16(dst, src) \
    asm volatile("cp.async.cg.shared.global [%0], [%1], 16;" :: "r"(dst), "l"(src))
#define CP_COMMIT() asm volatile("cp.async.commit_group;" ::: "memory")
#define CP_WAIT1()  asm volatile("cp.async.wait_group 1;" ::: "memory")

#define LDSM_X4(r0, r1, r2, r3, addr) \
    asm volatile("ldmatrix.sync.aligned.m8n8.x4.shared.b16 {%0,%1,%2,%3}, [%4];" \
        : "=r"(r0), "=r"(r1), "=r"(r2), "=r"(r3) : "r"(addr))

__device__ __forceinline__ void mma_f16(float* c, const uint32_t* a, const uint32_t* b) {
    asm volatile(
        "mma.sync.aligned.m16n8k16.row.col.f32.f16.f16.f32 "
        "{%0,%1,%2,%3}, {%4,%5,%6,%7}, {%8,%9}, {%0,%1,%2,%3};\n"
        : "+f"(c[0]), "+f"(c[1]), "+f"(c[2]), "+f"(c[3])
        : "r"(a[0]), "r"(a[1]), "r"(a[2]), "r"(a[3]), "r"(b[0]), "r"(b[1]));
}

// ---------- continuous-ring persistent fp16 GEMM, 2 CTAs/SM ----------
// C[M, N_TOTAL] = act(A[M,K] @ Wt[N,K]^T + bias). A, Wt fp16; accumulate fp32.
// BM=128, BN=128, BK=64 halves. 8 warps (4m x 2n), warp tile 32x64.
// All (tile, chunk) pairs per CTA form ONE chunk stream over a 3-stage cp.async
// ring: no per-tile drain/refill; epilogue overlaps next tile's loads.
template <int N_TOTAL, int K, bool RELU, bool HALF_OUT>
__global__ __launch_bounds__(256, 2)
void gemm_pipe_h(const __half* __restrict__ A, const __half* __restrict__ Wt,
                 const float* __restrict__ bias, void* __restrict__ Cv) {
    constexpr int BM = 128, BN = 128, BK = 64;     // BK in halves = 128 B
    constexpr int KCH = K / BK;
    constexpr int MI  = 2;                          // m16-frags per warp (32 rows)
    constexpr int P32 = 36;                         // u32 per smem row (72 halves, pad 8)
    constexpr int ROWB = P32 * 4;                   // 144 bytes
    constexpr int A_BYTES = BM * ROWB;              // 18432
    constexpr int B_BYTES = BN * ROWB;              // 18432
    constexpr int STAGE = A_BYTES + B_BYTES;        // 36864 (x3 = 110592)
    constexpr int NTX = N_TOTAL / BN;
    constexpr int NTILES = (M_TOTAL / BM) * NTX;

    extern __shared__ char smem[];
    const uint32_t sb = smem_u32(smem);

    const int tid  = threadIdx.x;
    const int warp = tid >> 5, lane = tid & 31;
    const int grp  = lane >> 2, tig = lane & 3;
    const int wm   = warp >> 1, wn = warp & 1;

    // ldmatrix per-lane byte offsets (tile-invariant)
    const int j  = lane >> 3;                       // 0..3
    const int r8 = lane & 7;
    uint32_t offA[MI], offB[4];
#pragma unroll
    for (int mi = 0; mi < MI; mi++)                 // A x4: (m0-7,k0-7)(m8-15,k0-7)(m0-7,k8-15)(m8-15,k8-15)
        offA[mi] = (uint32_t)((wm * 32 + mi * 16 + (j & 1) * 8 + r8) * ROWB + (j >> 1) * 16);
#pragma unroll
    for (int p = 0; p < 4; p++)                     // B pair: n-frags 2p, 2p+1
        offB[p] = (uint32_t)((wn * 64 + p * 16 + ((lane >> 4) & 1) * 8 + r8) * ROWB + ((lane >> 3) & 1) * 16);

    const int ldr = tid >> 3, ldc = tid & 7;        // stage-fill row/col

    // issue chunk c (global per-CTA chunk stream index) into ring stage c%3
    auto issue = [&](int c) {
        const int t  = blockIdx.x + (c / KCH) * gridDim.x;
        if (t >= NTILES) return;
        const int kt = c % KCH;
        const int bm = (t / NTX) * BM;
        const int bn = (t % NTX) * BN;
        const int k0 = kt * BK;
        const uint32_t ab = sb + (c % 3) * STAGE;
        const uint32_t bb = ab + A_BYTES;
#pragma unroll
        for (int i = 0; i < 4; i++) {
            int r = ldr + i * 32;
            CP_ASYNC16(ab + (uint32_t)(r * ROWB + ldc * 16),
                       A + (size_t)(bm + r) * K + k0 + ldc * 8);
        }
#pragma unroll
        for (int i = 0; i < 4; i++) {
            int r = ldr + i * 32;
            CP_ASYNC16(bb + (uint32_t)(r * ROWB + ldc * 16),
                       Wt + (size_t)(bn + r) * K + k0 + ldc * 8);
        }
    };

    // per-CTA tile count and total chunk stream length
    const int my_tiles = (NTILES - blockIdx.x + (int)gridDim.x - 1) / (int)gridDim.x;
    const int nch = my_tiles * KCH;
    if (nch == 0) return;

    float acc[MI][8][4];
#pragma unroll
    for (int mi = 0; mi < MI; mi++)
#pragma unroll
        for (int ni = 0; ni < 8; ni++)
#pragma unroll
            for (int q = 0; q < 4; q++) acc[mi][ni][q] = 0.0f;

    issue(0); CP_COMMIT();
    issue(1); CP_COMMIT();

    for (int g = 0; g < nch; g++) {
        const int s = g % 3;
        CP_WAIT1();                                 // chunk g landed
        __syncthreads();                            // chunk g-1 fully consumed by all warps
        issue(g + 2);                               // may belong to the next tile
        CP_COMMIT();

        const uint32_t sA = sb + s * STAGE;
        const uint32_t sB = sA + A_BYTES;
#pragma unroll
        for (int ks = 0; ks < 4; ks++) {            // 4 x k16 steps, +32B each
            const int kb = ks * 32;
            uint32_t a[MI][4], b[8][2];
#pragma unroll
            for (int mi = 0; mi < MI; mi++)
                LDSM_X4(a[mi][0], a[mi][1], a[mi][2], a[mi][3], sA + offA[mi] + kb);
#pragma unroll
            for (int p = 0; p < 4; p++)
                LDSM_X4(b[2 * p][0], b[2 * p][1], b[2 * p + 1][0], b[2 * p + 1][1],
                        sB + offB[p] + kb);
#pragma unroll
            for (int mi = 0; mi < MI; mi++)
#pragma unroll
                for (int ni = 0; ni < 8; ni++)
                    mma_f16(acc[mi][ni], a[mi], b[ni]);
        }

        // tile finished? -> epilogue (no smem; overlaps next tile's cp.async)
        if ((g % KCH) == KCH - 1) {
            const int t  = blockIdx.x + (g / KCH) * gridDim.x;
            const int bm = (t / NTX) * BM;
            const int bn = (t % NTX) * BN;
#pragma unroll
            for (int ni = 0; ni < 8; ni++) {
                const int n = bn + wn * 64 + ni * 8 + tig * 2;
                const float bv0 = __ldg(&bias[n]);
                const float bv1 = __ldg(&bias[n + 1]);
#pragma unroll
                for (int mi = 0; mi < MI; mi++) {
                    const int m0 = bm + wm * 32 + mi * 16 + grp;
                    float v0 = acc[mi][ni][0] + bv0;
                    float v1 = acc[mi][ni][1] + bv1;
                    float v2 = acc[mi][ni][2] + bv0;
                    float v3 = acc[mi][ni][3] + bv1;
                    if (RELU) {
                        v0 = fmaxf(v0, 0.0f); v1 = fmaxf(v1, 0.0f);
                        v2 = fmaxf(v2, 0.0f); v3 = fmaxf(v3, 0.0f);
                    }
                    if (HALF_OUT) {
                        __half* C = (__half*)Cv;
                        *(__half2*)(C + (size_t)m0 * N_TOTAL + n)       = __floats2half2_rn(v0, v1);
                        *(__half2*)(C + (size_t)(m0 + 8) * N_TOTAL + n) = __floats2half2_rn(v2, v3);
                    } else {
                        float* C = (float*)Cv;
                        *(float2*)(C + (size_t)m0 * N_TOTAL + n)       = make_float2(v0, v1);
                        *(float2*)(C + (size_t)(m0 + 8) * N_TOTAL + n) = make_float2(v2, v3);
                    }
                    acc[mi][ni][0] = 0.0f; acc[mi][ni][1] = 0.0f;
                    acc[mi][ni][2] = 0.0f; acc[mi][ni][3] = 0.0f;
                }
            }
        }
    }
}

// ---------------- merged prep kernel ----------------
// blocks [0, GB): gather emb[tok] -> fp16 x            (2 float4 per thread)
// blocks [GB, GB+256): cvt conv_w -> w0
// blocks [GB+256, GB+768): transpose+cvt w1 -> w1t
// blocks [GB+768, GB+896): transpose+cvt w2 -> w2t
#define GATHER_BLOCKS (M_TOTAL * EMBED / 8 / 256)   // 8192
__global__ __launch_bounds__(256)
void prep_kernel(const int* __restrict__ tok, const float* __restrict__ emb,
                 __half* __restrict__ x,
                 const float* __restrict__ conv_w, __half* __restrict__ w0,
                 const float* __restrict__ w1, __half* __restrict__ w1t,
                 const float* __restrict__ w2, __half* __restrict__ w2t) {
    const int b = blockIdx.x;
    const int tid = threadIdx.x;
    if (b < GATHER_BLOCKS) {
        const int base = (b * 256 + tid) * 2;
#pragma unroll
        for (int u = 0; u < 2; u++) {
            const int i4 = base + u;
            const int row = i4 >> 7;                // EMBED/4 = 128
            const int c   = (i4 & 127) << 2;
            const float4 v = *(const float4*)(emb + (size_t)tok[row] * EMBED + c);
            __half2 h0 = __floats2half2_rn(v.x, v.y);
            __half2 h1 = __floats2half2_rn(v.z, v.w);
            *(uint2*)(x + (size_t)row * EMBED + c) = make_uint2(*(uint32_t*)&h0, *(uint32_t*)&h1);
        }
        return;
    }
    const int wb = b - GATHER_BLOCKS;
    if (wb < 256) {                                 // cvt conv_w
        const int i4 = wb * 256 + tid;
        const float4 v = *(const float4*)(conv_w + (size_t)i4 * 4);
        __half2 h0 = __floats2half2_rn(v.x, v.y);
        __half2 h1 = __floats2half2_rn(v.z, v.w);
        *(uint2*)(w0 + (size_t)i4 * 4) = make_uint2(*(uint32_t*)&h0, *(uint32_t*)&h1);
        return;
    }
    const float* in; __half* outp; int R, Ccols, tb;
    if (wb < 768) { in = w1; outp = w1t; R = CONVC; Ccols = HID;    tb = wb - 256; }
    else          { in = w2; outp = w2t; R = HID;   Ccols = LABELS; tb = wb - 768; }
    const int tpr = Ccols / 32;
    const int by = (tb / tpr) * 32, bx = (tb % tpr) * 32;
    const int tx = tid & 31, ty = tid >> 5;
    __shared__ float t[32][33];
    int x2 = bx + tx;
#pragma unroll
    for (int jj = 0; jj < 32; jj += 8) {
        int y = by + ty + jj;
        t[ty + jj][tx] = in[(size_t)y * Ccols + x2];
    }
    __syncthreads();
    x2 = by + tx;
#pragma unroll
    for (int jj = 0; jj < 32; jj += 8) {
        int y = bx + ty + jj;
        outp[(size_t)y * R + x2] = __float2half_rn(t[tx][ty + jj]);
    }
}

extern "C" void kernel_launch(void* const* d_in, const int* in_sizes, int n_in,
                              void* d_out, int out_size) {
    const int*   tok    = (const int*)d_in[0];
    const float* emb    = (const float*)d_in[1];
    const float* conv_w = (const float*)d_in[2];   // [CONVC, EMBED] = [N,K]
    const float* conv_b = (const float*)d_in[3];
    const float* w1     = (const float*)d_in[4];   // [CONVC, HID]
    const float* b1     = (const float*)d_in[5];
    const float* w2     = (const float*)d_in[6];   // [HID, LABELS]
    const float* b2     = (const float*)d_in[7];
    float* out = (float*)d_out;

    __half *x_buf, *h_buf, *z_buf, *w0, *w1t, *w2t;
    cudaGetSymbolAddress((void**)&x_buf, g_x);
    cudaGetSymbolAddress((void**)&h_buf, g_h);
    cudaGetSymbolAddress((void**)&z_buf, g_z);
    cudaGetSymbolAddress((void**)&w0,  g_w0);
    cudaGetSymbolAddress((void**)&w1t, g_w1t);
    cudaGetSymbolAddress((void**)&w2t, g_w2t);

    constexpr int SMEM = 3 * (128 * 144 + 128 * 144);   // 110592 -> 2 CTAs/SM
    cudaFuncSetAttribute(gemm_pipe_h<CONVC, EMBED, true,  true>,
                         cudaFuncAttributeMaxDynamicSharedMemorySize, SMEM);
    cudaFuncSetAttribute(gemm_pipe_h<HID, CONVC, true,  true>,
                         cudaFuncAttributeMaxDynamicSharedMemorySize, SMEM);
    cudaFuncSetAttribute(gemm_pipe_h<LABELS, HID, false, false>,
                         cudaFuncAttributeMaxDynamicSharedMemorySize, SMEM);

    constexpr int PERSIST = 296;                    // 148 SMs x 2 CTAs

    // Prep (one kernel: gather + all weight conversions)
    prep_kernel<<<GATHER_BLOCKS + 896, 256>>>(tok, emb, x_buf, conv_w, w0, w1, w1t, w2, w2t);

    // GEMM1: h = fp16(relu(x @ conv_w^T + conv_b))    [32768, 512], 1024 tiles
    gemm_pipe_h<CONVC, EMBED, true, true>
        <<<PERSIST, 256, SMEM>>>(x_buf, w0, conv_b, h_buf);
    // GEMM2: z = fp16(relu(h @ w1 + b1))              [32768, 1024], 2048 tiles
    gemm_pipe_h<HID, CONVC, true, true>
        <<<PERSIST, 256, SMEM>>>(h_buf, w1t, b1, z_buf);
    // GEMM3: out = z @ w2 + b2                        [32768, 128], 256 tiles
    gemm_pipe_h<LABELS, HID, false, false>
        <<<256, 256, SMEM>>>(z_buf, w2t, b2, out);
}